// round 4
// baseline (speedup 1.0000x reference)
#include <cuda_runtime.h>
#include <cstdint>

// GCN FeatureDiscriminator: B=256, V=512, F=256, O=2
// Pipelined: A (streaming, 4 chunks on capture stream) overlapped with
// B (aggregation, forked stream, 4 CTAs/batch) via captured events.

#define BATCH 256
#define BV 512
#define BF 256
#define NROWS (BATCH * BV)
#define NTHREADS 512
#define NWARP 16
#define GRID_A 304
#define TOTAL_WARPS_A (GRID_A * NWARP)
#define NCHUNK 4
#define BATCH_PER_CHUNK (BATCH / NCHUNK)          // 64
#define ROWS_PER_CHUNK (NROWS / NCHUNK)           // 32768
#define PARTS 4                                    // CTAs per batch in B
#define ROWS_PER_PART (BV / PARTS)                 // 128

__device__ unsigned g_bits[NROWS * 16];   // 8 MB: 512-bit mask per row
__device__ float    g_dinv[NROWS];
__device__ float2   g_sxw[NROWS];         // dinv[w] * (X[w,:] @ W)
__device__ float    g_part[BATCH * PARTS];

// ---------------------------------------------------------------------------
// Kernel A: warp per row, grid-stride within chunk.
// Bit convention: bits[row][4c+k] bit 'l'  <->  column w = 128*c + 4*l + k
// ---------------------------------------------------------------------------
__global__ __launch_bounds__(NTHREADS, 2)
void gcn_rows_kernel(const float* __restrict__ features,
                     const int*   __restrict__ graphs,
                     const float* __restrict__ conv_weight,   // [F,2]
                     int row_base)
{
    const int tid  = threadIdx.x;
    const int wid  = tid >> 5;
    const int lane = tid & 31;
    const int gwarp = blockIdx.x * NWARP + wid;

    float w0r[8], w1r[8];
    {
        const float2* cw2 = (const float2*)conv_weight;
        #pragma unroll
        for (int j = 0; j < 8; j++) {
            float2 w = __ldg(cw2 + 8 * lane + j);
            w0r[j] = w.x; w1r[j] = w.y;
        }
    }

    const int row_end = row_base + ROWS_PER_CHUNK;
    for (int row = row_base + gwarp; row < row_end; row += TOTAL_WARPS_A) {
        const int v = row & (BV - 1);
        const int4*   grow = (const int4*)graphs + (size_t)row * (BV / 4);
        const float4* frow = (const float4*)features + (size_t)row * (BF / 4);

        int4 x0 = __ldcs(grow + 0 * 32 + lane);
        int4 x1 = __ldcs(grow + 1 * 32 + lane);
        int4 x2 = __ldcs(grow + 2 * 32 + lane);
        int4 x3 = __ldcs(grow + 3 * 32 + lane);
        float4 fa = __ldcs(frow + 2 * lane);
        float4 fb = __ldcs(frow + 2 * lane + 1);

        int deg = 0;
        #pragma unroll
        for (int c = 0; c < 4; c++) {
            int4 x = (c == 0) ? x0 : (c == 1) ? x1 : (c == 2) ? x2 : x3;
            int w0 = 128 * c + 4 * lane;
            unsigned m0 = __ballot_sync(0xffffffffu, (x.x != 0) || (w0     == v));
            unsigned m1 = __ballot_sync(0xffffffffu, (x.y != 0) || (w0 + 1 == v));
            unsigned m2 = __ballot_sync(0xffffffffu, (x.z != 0) || (w0 + 2 == v));
            unsigned m3 = __ballot_sync(0xffffffffu, (x.w != 0) || (w0 + 3 == v));
            deg += __popc(m0) + __popc(m1) + __popc(m2) + __popc(m3);
            if (lane == c) {
                ((uint4*)g_bits)[(size_t)row * 4 + c] = make_uint4(m0, m1, m2, m3);
            }
        }

        float acc0 = fa.x * w0r[0];             float acc1 = fa.x * w1r[0];
        acc0 = fmaf(fa.y, w0r[1], acc0);        acc1 = fmaf(fa.y, w1r[1], acc1);
        acc0 = fmaf(fa.z, w0r[2], acc0);        acc1 = fmaf(fa.z, w1r[2], acc1);
        acc0 = fmaf(fa.w, w0r[3], acc0);        acc1 = fmaf(fa.w, w1r[3], acc1);
        acc0 = fmaf(fb.x, w0r[4], acc0);        acc1 = fmaf(fb.x, w1r[4], acc1);
        acc0 = fmaf(fb.y, w0r[5], acc0);        acc1 = fmaf(fb.y, w1r[5], acc1);
        acc0 = fmaf(fb.z, w0r[6], acc0);        acc1 = fmaf(fb.z, w1r[6], acc1);
        acc0 = fmaf(fb.w, w0r[7], acc0);        acc1 = fmaf(fb.w, w1r[7], acc1);
        #pragma unroll
        for (int s = 16; s; s >>= 1) {
            acc0 += __shfl_xor_sync(0xffffffffu, acc0, s);
            acc1 += __shfl_xor_sync(0xffffffffu, acc1, s);
        }
        if (lane == 0) {
            float d = rsqrtf((float)deg);        // deg >= 1 (self-loop)
            g_dinv[row] = d;
            g_sxw[row]  = make_float2(d * acc0, d * acc1);
        }
    }
}

// ---------------------------------------------------------------------------
// Kernel B: 4 CTAs per batch, 128 rows each. Proven round-2 inner loop.
// ---------------------------------------------------------------------------
__global__ __launch_bounds__(NTHREADS, 2)
void gcn_agg_kernel(const float* __restrict__ conv_bias,
                    const float* __restrict__ lin_weight,   // [2v+o]
                    int batch_base)
{
    __shared__ unsigned bits[ROWS_PER_PART][16];   // 8 KB
    __shared__ float s0[BV];
    __shared__ float s1[BV];
    __shared__ float dinv_s[ROWS_PER_PART];
    __shared__ float lw_s[ROWS_PER_PART * 2];
    __shared__ float wpart[NWARP];

    const int b    = batch_base + (blockIdx.x >> 2);
    const int part = blockIdx.x & 3;
    const int tid  = threadIdx.x;
    const int wid  = tid >> 5;
    const int lane = tid & 31;

    // ---- stage (coalesced) ----
    {
        const uint4* src = (const uint4*)g_bits + (size_t)b * (BV * 4)
                         + (size_t)part * (ROWS_PER_PART * 4);
        ((uint4*)bits)[tid] = src[tid];

        float2 xw = g_sxw[b * BV + tid];           // already dinv-scaled
        s0[tid] = xw.x;
        s1[tid] = xw.y;

        if (tid < ROWS_PER_PART)
            dinv_s[tid] = g_dinv[b * BV + part * ROWS_PER_PART + tid];
        if (tid < ROWS_PER_PART * 2)
            lw_s[tid] = lin_weight[b * 0 + part * ROWS_PER_PART * 2 + tid];
    }
    __syncthreads();

    // preload this lane's fixed 16 s pairs: w = 128*c + 4*lane + k
    float r0[16], r1[16];
    #pragma unroll
    for (int c = 0; c < 4; c++)
        #pragma unroll
        for (int k = 0; k < 4; k++) {
            int w = 128 * c + 4 * lane + k;
            r0[4 * c + k] = s0[w];
            r1[4 * c + k] = s1[w];
        }

    const float cb0 = conv_bias[0];
    const float cb1 = conv_bias[1];

    float acc_part = 0.0f;
    #pragma unroll
    for (int r = 0; r < ROWS_PER_PART / NWARP; r++) {     // 8 rows per warp
        const int vl = wid * (ROWS_PER_PART / NWARP) + r;
        float acc0 = 0.0f, acc1 = 0.0f;
        #pragma unroll
        for (int j = 0; j < 16; j++) {
            unsigned m = bits[vl][j];                      // broadcast LDS
            if ((m >> lane) & 1u) {
                acc0 += r0[j];
                acc1 += r1[j];
            }
        }
        #pragma unroll
        for (int s = 16; s; s >>= 1) {
            acc0 += __shfl_xor_sync(0xffffffffu, acc0, s);
            acc1 += __shfl_xor_sync(0xffffffffu, acc1, s);
        }
        if (lane == 0) {
            float d  = dinv_s[vl];
            float h0 = fmaxf(fmaf(d, acc0, cb0), 0.0f);
            float h1 = fmaxf(fmaf(d, acc1, cb1), 0.0f);
            acc_part = fmaf(h0, lw_s[2 * vl], acc_part);
            acc_part = fmaf(h1, lw_s[2 * vl + 1], acc_part);
        }
    }
    if (lane == 0) wpart[wid] = acc_part;
    __syncthreads();

    if (wid == 0) {
        float s = (lane < NWARP) ? wpart[lane] : 0.0f;
        #pragma unroll
        for (int sh = 8; sh; sh >>= 1) s += __shfl_xor_sync(0xffffffffu, s, sh);
        if (lane == 0) g_part[b * PARTS + part] = s;
    }
}

// ---------------------------------------------------------------------------
// Final: sum 4 partials per batch + bias, sigmoid.
// ---------------------------------------------------------------------------
__global__ void gcn_fin_kernel(const float* __restrict__ lin_bias,
                               float* __restrict__ out)
{
    int b = threadIdx.x;
    float4 p = ((const float4*)g_part)[b];
    float logit = (p.x + p.y) + (p.z + p.w) + lin_bias[0];
    out[b] = 1.0f / (1.0f + expf(-logit));
}

extern "C" void kernel_launch(void* const* d_in, const int* in_sizes, int n_in,
                              void* d_out, int out_size) {
    const float* features    = (const float*)d_in[0];
    const int*   graphs      = (const int*)  d_in[1];
    const float* conv_weight = (const float*)d_in[2];
    const float* conv_bias   = (const float*)d_in[3];
    const float* lin_weight  = (const float*)d_in[4];
    const float* lin_bias    = (const float*)d_in[5];
    float* out = (float*)d_out;

    // one-time creation (first call is the uncaptured correctness run)
    static cudaStream_t s1;
    static cudaEvent_t evA[NCHUNK], evJoin;
    static int init_done = 0;
    if (!init_done) {
        cudaStreamCreateWithFlags(&s1, cudaStreamNonBlocking);
        for (int k = 0; k < NCHUNK; k++)
            cudaEventCreateWithFlags(&evA[k], cudaEventDisableTiming);
        cudaEventCreateWithFlags(&evJoin, cudaEventDisableTiming);
        init_done = 1;
    }

    for (int k = 0; k < NCHUNK; k++) {
        gcn_rows_kernel<<<GRID_A, NTHREADS>>>(features, graphs, conv_weight,
                                              k * ROWS_PER_CHUNK);
        cudaEventRecord(evA[k], 0);
        cudaStreamWaitEvent(s1, evA[k], 0);
        gcn_agg_kernel<<<BATCH_PER_CHUNK * PARTS, NTHREADS, 0, s1>>>(
            conv_bias, lin_weight, k * BATCH_PER_CHUNK);
    }
    cudaEventRecord(evJoin, s1);
    cudaStreamWaitEvent((cudaStream_t)0, evJoin, 0);
    gcn_fin_kernel<<<1, BATCH>>>(lin_bias, out);
}